// round 9
// baseline (speedup 1.0000x reference)
#include <cuda_runtime.h>
#include <cuda_fp16.h>
#include <cstdint>

// Problem constants
#define D1_  270
#define K_   32
#define C_   60
#define B_   64
#define T_   4096
#define P_   (K_*K_)          // 1024

// ---------------- device scratch (no allocation; zero-initialized) ----------
__device__ float g_ct[P_ * C_];     // cos(phase)[p][c]
__device__ float g_st[P_ * C_];     // sin(phase)[p][c]

// fp16 operands; all padding (c>=60, j>=270, c rows 60..63 of X) stays at the
// zero-init value of device globals and is never written.
__device__ __align__(16) __half g_wh[3 * 96 * 72];                 // [jb][row][c pad 72]
__device__ __align__(16) __half g_xh[(size_t)B_ * 64 * T_];        // [b][c pad 64][t]
__device__ __align__(16) __half g_xl[(size_t)B_ * 64 * T_];

// ---------------- kernel 1: trig tables (double frac + sincosf) -------------
__global__ void trig_kernel(const float* __restrict__ loc) {
    int i = blockIdx.x * 256 + threadIdx.x;
    if (i >= P_ * C_) return;
    int p = i / C_, c = i - p * C_;
    int k = p >> 5, l = p & 31;
    double r = (double)k * (double)loc[2 * c] + (double)l * (double)loc[2 * c + 1];
    double fr = r - floor(r);                      // exact range reduction
    float ph = (float)(6.283185307179586476925286766559 * fr);
    float s, co;
    sincosf(ph, &s, &co);
    g_ct[i] = co;
    g_st[i] = s;
}

// ---------------- kernel 2: X -> fp16 hi/lo (c rows 60..63 stay zero) -------
__global__ void xsplit_kernel(const float* __restrict__ X) {
    int idx = blockIdx.x * 256 + threadIdx.x;     // over B*60*(T/2)
    if (idx >= B_ * C_ * (T_ / 2)) return;
    int t2 = idx % (T_ / 2);
    int cc = (idx / (T_ / 2)) % C_;
    int b  = idx / ((T_ / 2) * C_);
    float2 v = *(const float2*)(X + ((size_t)(b * C_ + cc)) * T_ + t2 * 2);
    __half2 h = __floats2half2_rn(v.x, v.y);
    float r0 = v.x - __half2float(h.x);
    float r1 = v.y - __half2float(h.y);
    __half2 l = __floats2half2_rn(r0, r1);
    size_t o = ((size_t)(b * 64 + cc) * T_ + t2 * 2) * 2;   // byte offset
    *(uint32_t*)((char*)g_xh + o) = *(uint32_t*)&h;
    *(uint32_t*)((char*)g_xl + o) = *(uint32_t*)&l;
}

// ---------------- kernel 3: weights + softmax -> fp16 W tile ----------------
#define JB 6
__global__ void weights_kernel(const float* __restrict__ zre,
                               const float* __restrict__ zim) {
    int jb = blockIdx.x * JB;
    int tid = threadIdx.x;
    int s = tid >> 6, c = tid & 63;

    float acc[JB];
    #pragma unroll
    for (int u = 0; u < JB; u++) acc[u] = 0.f;

    if (c < C_) {
        int p0 = s * 256;
        for (int p = p0; p < p0 + 256; p++) {
            float ct = g_ct[p * C_ + c];
            float st = g_st[p * C_ + c];
            #pragma unroll
            for (int u = 0; u < JB; u++) {
                acc[u] += zre[(jb + u) * P_ + p] * ct + zim[(jb + u) * P_ + p] * st;
            }
        }
    }

    __shared__ float part[JB][4][64];
    __shared__ float ex[JB][64];
    __shared__ float tot[JB];
    #pragma unroll
    for (int u = 0; u < JB; u++) part[u][s][c] = acc[u];
    __syncthreads();
    if (s == 0 && c < C_) {
        #pragma unroll
        for (int u = 0; u < JB; u++) {
            float a = part[u][0][c] + part[u][1][c] + part[u][2][c] + part[u][3][c];
            ex[u][c] = expf(a);
        }
    }
    __syncthreads();
    if (tid < JB) {
        float t = 0.f;
        #pragma unroll
        for (int i = 0; i < C_; i++) t += ex[tid][i];
        tot[tid] = t;
    }
    __syncthreads();
    if (s == 0 && c < C_) {
        #pragma unroll
        for (int u = 0; u < JB; u++) {
            int j = jb + u;
            g_wh[(j / 96) * (96 * 72) + (j % 96) * 72 + c] =
                __float2half(ex[u][c] / tot[u]);
        }
    }
}

// ---------------- kernel 4: HMMA GEMM fp16 2-pass, 96j x 128t tiles ---------
// smem: WH[96 x 144B] | XH[64 x 272B] XL[64 x 272B]  (48640 B static)
#define ROWW  144
#define ROWX  272
#define WHo   0
#define XHo   13824
#define XLo   (13824 + 64 * ROWX)       // 31232
#define SMEMB (13824 + 2 * 64 * ROWX)   // 48640

__device__ __forceinline__ uint32_t smem_u32(const void* p) {
    uint32_t a;
    asm("{ .reg .u64 t; cvta.to.shared.u64 t, %1; cvt.u32.u64 %0, t; }"
        : "=r"(a) : "l"(p));
    return a;
}
__device__ __forceinline__ void cpa16(uint32_t dst, const void* src) {
    asm volatile("cp.async.cg.shared.global [%0], [%1], 16;"
                 :: "r"(dst), "l"(src) : "memory");
}
__device__ __forceinline__ void ldm_x4(uint32_t* r, uint32_t addr) {
    asm volatile("ldmatrix.sync.aligned.m8n8.x4.shared.b16 {%0,%1,%2,%3}, [%4];"
                 : "=r"(r[0]), "=r"(r[1]), "=r"(r[2]), "=r"(r[3]) : "r"(addr));
}
__device__ __forceinline__ void ldm_x4t(uint32_t* r, uint32_t addr) {
    asm volatile("ldmatrix.sync.aligned.m8n8.x4.trans.shared.b16 {%0,%1,%2,%3}, [%4];"
                 : "=r"(r[0]), "=r"(r[1]), "=r"(r[2]), "=r"(r[3]) : "r"(addr));
}
__device__ __forceinline__ void mma_f16(float* d, const uint32_t* a, const uint32_t* b) {
    asm volatile(
        "mma.sync.aligned.m16n8k16.row.col.f32.f16.f16.f32 "
        "{%0,%1,%2,%3}, {%4,%5,%6,%7}, {%8,%9}, {%0,%1,%2,%3};"
        : "+f"(d[0]), "+f"(d[1]), "+f"(d[2]), "+f"(d[3])
        : "r"(a[0]), "r"(a[1]), "r"(a[2]), "r"(a[3]), "r"(b[0]), "r"(b[1]));
}

__global__ void __launch_bounds__(192)
mma_kernel(float* __restrict__ out) {
    __shared__ __align__(16) char sm[SMEMB];
    uint32_t smb = smem_u32(sm);

    int tid = threadIdx.x, wid = tid >> 5, lane = tid & 31;
    int t0 = blockIdx.x * 128;
    int jb = blockIdx.y;
    int j0 = jb * 96;
    int b  = blockIdx.z;

    // ---- stage W (864 x 16B) and X hi/lo (2 x 1024 x 16B), pure copies ----
    const char* wh = (const char*)(g_wh + jb * 96 * 72);
    for (int i = tid; i < 864; i += 192)
        cpa16(smb + WHo + i * 16, wh + i * 16);

    const char* xh = (const char*)(g_xh + (size_t)(b * 64) * T_ + t0);
    const char* xl = (const char*)(g_xl + (size_t)(b * 64) * T_ + t0);
    for (int i = tid; i < 1024; i += 192) {
        int row = i >> 4, o = (i & 15) * 16;
        cpa16(smb + XHo + row * ROWX + o, xh + (size_t)row * T_ * 2 + o);
        cpa16(smb + XLo + row * ROWX + o, xl + (size_t)row * T_ * 2 + o);
    }
    asm volatile("cp.async.commit_group;" ::: "memory");
    asm volatile("cp.async.wait_group 0;" ::: "memory");
    __syncthreads();

    // ---- main: warp (wj 0..2, wt 0..1) -> 32j x 64t ----
    int wj = wid >> 1, wt = wid & 1;
    int r  = lane & 7, mi = lane >> 3;

    int arow  = wj * 32 + (mi & 1) * 8 + r;        // + jf*16  (A non-trans)
    int acoff = (mi >> 1) * 8;
    int bcrow = (mi & 1) * 8 + r;                  // B trans, proven R8 mapping
    int btoff = (wt * 64 + (mi >> 1) * 8) * 2;

    float acc[2][8][4];
    #pragma unroll
    for (int jf = 0; jf < 2; jf++)
        #pragma unroll
        for (int nf = 0; nf < 8; nf++)
            #pragma unroll
            for (int q = 0; q < 4; q++) acc[jf][nf][q] = 0.f;

    #pragma unroll
    for (int k = 0; k < 4; k++) {
        uint32_t Ah[2][4];
        #pragma unroll
        for (int jf = 0; jf < 2; jf++) {
            uint32_t off = (uint32_t)((arow + jf * 16) * ROWW + (k * 16 + acoff) * 2);
            ldm_x4(Ah[jf], smb + WHo + off);
        }
        #pragma unroll
        for (int nt = 0; nt < 4; nt++) {
            uint32_t off = (uint32_t)((k * 16 + bcrow) * ROWX + btoff + nt * 32);
            uint32_t rh[4], rl[4];
            ldm_x4t(rh, smb + XHo + off);
            ldm_x4t(rl, smb + XLo + off);
            #pragma unroll
            for (int jf = 0; jf < 2; jf++) {
                mma_f16(acc[jf][2*nt],   Ah[jf], rh);        // hi * xhi
                mma_f16(acc[jf][2*nt+1], Ah[jf], rh + 2);
                mma_f16(acc[jf][2*nt],   Ah[jf], rl);        // hi * xlo
                mma_f16(acc[jf][2*nt+1], Ah[jf], rl + 2);
            }
        }
    }

    // ---- epilogue: float2 stores, predicated on j < 270 ----
    int g = lane >> 2, q2 = (lane & 3) * 2;
    #pragma unroll
    for (int jf = 0; jf < 2; jf++) {
        int j = j0 + wj * 32 + jf * 16 + g;
        #pragma unroll
        for (int nf = 0; nf < 8; nf++) {
            int t = t0 + wt * 64 + nf * 8 + q2;
            if (j < D1_) {
                float2 v0 = make_float2(acc[jf][nf][0], acc[jf][nf][1]);
                *(float2*)(out + ((size_t)b * D1_ + j) * T_ + t) = v0;
            }
            if (j + 8 < D1_) {
                float2 v1 = make_float2(acc[jf][nf][2], acc[jf][nf][3]);
                *(float2*)(out + ((size_t)b * D1_ + j + 8) * T_ + t) = v1;
            }
        }
    }
}

// ---------------- launch ----------------
extern "C" void kernel_launch(void* const* d_in, const int* in_sizes, int n_in,
                              void* d_out, int out_size) {
    const float* X   = (const float*)d_in[0];   // [64, 60, 4096]
    const float* zre = (const float*)d_in[1];   // [270, 32, 32]
    const float* zim = (const float*)d_in[2];   // [270, 32, 32]
    const float* loc = (const float*)d_in[3];   // [60, 2]
    float* out = (float*)d_out;                 // [64, 270, 4096]

    trig_kernel<<<(P_ * C_ + 255) / 256, 256>>>(loc);
    xsplit_kernel<<<(B_ * C_ * (T_ / 2) + 255) / 256, 256>>>(X);
    weights_kernel<<<D1_ / JB, 256>>>(zre, zim);
    dim3 grid(T_ / 128, 3, B_);   // t fastest -> X[b] stays L2-resident across jb
    mma_kernel<<<grid, 192>>>(out);
}

// round 10
// speedup vs baseline: 1.3104x; 1.3104x over previous
#include <cuda_runtime.h>
#include <cuda_fp16.h>
#include <cstdint>

// Problem constants
#define D1_  270
#define K_   32
#define C_   60
#define B_   64
#define T_   4096
#define P_   (K_*K_)          // 1024

// ---------------- device scratch (no allocation; zero-initialized) ----------
// trig tables TRANSPOSED: [c pad 64][p 1024] for vectorized weights reads
__device__ float g_ct[64 * 1024];
__device__ float g_st[64 * 1024];
// fp16 W tile, ldmatrix-ready: [jb][row 96][c pad 72]; padding stays zero-init
__device__ __align__(16) __half g_wh[3 * 96 * 72];

// ---------------- kernel 1: trig tables (double frac + sincosf) -------------
__global__ void trig_kernel(const float* __restrict__ loc) {
    int i = blockIdx.x * 256 + threadIdx.x;
    if (i >= 64 * 1024) return;
    int c = i >> 10, p = i & 1023;
    float co = 0.f, s = 0.f;
    if (c < C_) {
        int k = p >> 5, l = p & 31;
        double r = (double)k * (double)loc[2 * c] + (double)l * (double)loc[2 * c + 1];
        double fr = r - floor(r);                  // exact range reduction
        float ph = (float)(6.283185307179586476925286766559 * fr);
        sincosf(ph, &s, &co);
    }
    g_ct[i] = co;
    g_st[i] = s;
}

// ---------------- kernel 2: weights + softmax -> fp16 W tile (float4 loads) -
#define JB 6
__global__ void weights_kernel(const float* __restrict__ zre,
                               const float* __restrict__ zim) {
    int jb = blockIdx.x * JB;
    int tid = threadIdx.x;
    int s = tid >> 6, c = tid & 63;

    float acc[JB];
    #pragma unroll
    for (int u = 0; u < JB; u++) acc[u] = 0.f;

    if (c < C_) {
        int p0 = s * 256;
        #pragma unroll 2
        for (int p = p0; p < p0 + 256; p += 4) {
            float4 ct = *(const float4*)&g_ct[c * 1024 + p];
            float4 st = *(const float4*)&g_st[c * 1024 + p];
            #pragma unroll
            for (int u = 0; u < JB; u++) {
                float4 zr = *(const float4*)&zre[(jb + u) * P_ + p];
                float4 zi = *(const float4*)&zim[(jb + u) * P_ + p];
                acc[u] += zr.x * ct.x + zr.y * ct.y + zr.z * ct.z + zr.w * ct.w
                        + zi.x * st.x + zi.y * st.y + zi.z * st.z + zi.w * st.w;
            }
        }
    }

    __shared__ float part[JB][4][64];
    __shared__ float ex[JB][64];
    __shared__ float tot[JB];
    #pragma unroll
    for (int u = 0; u < JB; u++) part[u][s][c] = acc[u];
    __syncthreads();
    if (s == 0 && c < C_) {
        #pragma unroll
        for (int u = 0; u < JB; u++) {
            float a = part[u][0][c] + part[u][1][c] + part[u][2][c] + part[u][3][c];
            ex[u][c] = expf(a);
        }
    }
    __syncthreads();
    if (tid < JB) {
        float t = 0.f;
        #pragma unroll
        for (int i = 0; i < C_; i++) t += ex[tid][i];
        tot[tid] = t;
    }
    __syncthreads();
    if (s == 0 && c < C_) {
        #pragma unroll
        for (int u = 0; u < JB; u++) {
            int j = jb + u;
            g_wh[(j / 96) * (96 * 72) + (j % 96) * 72 + c] =
                __float2half(ex[u][c] / tot[u]);
        }
    }
}

// ---------------- kernel 3: HMMA GEMM fp16 2-pass, in-kernel X conversion ---
// smem: WH[96 x 144B] | XH[64 x 272B] XL[64 x 272B]  (48640 B static)
#define ROWW  144
#define ROWX  272
#define WHo   0
#define XHo   13824
#define XLo   (13824 + 64 * ROWX)       // 31232
#define SMEMB (13824 + 2 * 64 * ROWX)   // 48640

__device__ __forceinline__ uint32_t smem_u32(const void* p) {
    uint32_t a;
    asm("{ .reg .u64 t; cvta.to.shared.u64 t, %1; cvt.u32.u64 %0, t; }"
        : "=r"(a) : "l"(p));
    return a;
}
__device__ __forceinline__ void cpa16(uint32_t dst, const void* src) {
    asm volatile("cp.async.cg.shared.global [%0], [%1], 16;"
                 :: "r"(dst), "l"(src) : "memory");
}
__device__ __forceinline__ void ldm_x4(uint32_t* r, uint32_t addr) {
    asm volatile("ldmatrix.sync.aligned.m8n8.x4.shared.b16 {%0,%1,%2,%3}, [%4];"
                 : "=r"(r[0]), "=r"(r[1]), "=r"(r[2]), "=r"(r[3]) : "r"(addr));
}
__device__ __forceinline__ void ldm_x4t(uint32_t* r, uint32_t addr) {
    asm volatile("ldmatrix.sync.aligned.m8n8.x4.trans.shared.b16 {%0,%1,%2,%3}, [%4];"
                 : "=r"(r[0]), "=r"(r[1]), "=r"(r[2]), "=r"(r[3]) : "r"(addr));
}
__device__ __forceinline__ void mma_f16(float* d, const uint32_t* a, const uint32_t* b) {
    asm volatile(
        "mma.sync.aligned.m16n8k16.row.col.f32.f16.f16.f32 "
        "{%0,%1,%2,%3}, {%4,%5,%6,%7}, {%8,%9}, {%0,%1,%2,%3};"
        : "+f"(d[0]), "+f"(d[1]), "+f"(d[2]), "+f"(d[3])
        : "r"(a[0]), "r"(a[1]), "r"(a[2]), "r"(a[3]), "r"(b[0]), "r"(b[1]));
}

__global__ void __launch_bounds__(192)
mma_kernel(const float* __restrict__ X, float* __restrict__ out) {
    __shared__ __align__(16) char sm[SMEMB];
    uint32_t smb = smem_u32(sm);

    int tid = threadIdx.x, wid = tid >> 5, lane = tid & 31;
    int t0 = blockIdx.x * 128;
    int jb = blockIdx.y;
    int j0 = jb * 96;
    int b  = blockIdx.z;

    // ---- stage W (864 x 16B, pure async copy) ----
    const char* wh = (const char*)(g_wh + jb * 96 * 72);
    for (int i = tid; i < 864; i += 192)
        cpa16(smb + WHo + i * 16, wh + i * 16);
    asm volatile("cp.async.commit_group;" ::: "memory");

    // ---- stage X: fp32 LDG.128 -> fp16 hi/lo split -> STS ----
    // tile = 64 c-rows x 128 t = 2048 float4 chunks (rows >= 60 are zeros)
    const float* Xb = X + (size_t)b * C_ * T_ + t0;
    #pragma unroll 1
    for (int i = tid; i < 2048; i += 192) {
        int row = i >> 5, q = i & 31;           // q: float4 index along t
        float4 v = make_float4(0.f, 0.f, 0.f, 0.f);
        if (row < C_) v = *(const float4*)(Xb + (size_t)row * T_ + q * 4);
        __half2 h0 = __floats2half2_rn(v.x, v.y);
        __half2 h1 = __floats2half2_rn(v.z, v.w);
        __half2 l0 = __floats2half2_rn(v.x - __half2float(h0.x),
                                       v.y - __half2float(h0.y));
        __half2 l1 = __floats2half2_rn(v.z - __half2float(h1.x),
                                       v.w - __half2float(h1.y));
        uint2 hh = make_uint2(*(uint32_t*)&h0, *(uint32_t*)&h1);
        uint2 ll = make_uint2(*(uint32_t*)&l0, *(uint32_t*)&l1);
        *(uint2*)(sm + XHo + row * ROWX + q * 8) = hh;
        *(uint2*)(sm + XLo + row * ROWX + q * 8) = ll;
    }
    asm volatile("cp.async.wait_group 0;" ::: "memory");
    __syncthreads();

    // ---- main: warp (wj 0..2, wt 0..1) -> 32j x 64t (proven R9 mapping) ----
    int wj = wid >> 1, wt = wid & 1;
    int r  = lane & 7, mi = lane >> 3;

    int arow  = wj * 32 + (mi & 1) * 8 + r;        // + jf*16  (A non-trans)
    int acoff = (mi >> 1) * 8;
    int bcrow = (mi & 1) * 8 + r;                  // B trans
    int btoff = (wt * 64 + (mi >> 1) * 8) * 2;

    float acc[2][8][4];
    #pragma unroll
    for (int jf = 0; jf < 2; jf++)
        #pragma unroll
        for (int nf = 0; nf < 8; nf++)
            #pragma unroll
            for (int q = 0; q < 4; q++) acc[jf][nf][q] = 0.f;

    #pragma unroll
    for (int k = 0; k < 4; k++) {
        uint32_t Ah[2][4];
        #pragma unroll
        for (int jf = 0; jf < 2; jf++) {
            uint32_t off = (uint32_t)((arow + jf * 16) * ROWW + (k * 16 + acoff) * 2);
            ldm_x4(Ah[jf], smb + WHo + off);
        }
        #pragma unroll
        for (int nt = 0; nt < 4; nt++) {
            uint32_t off = (uint32_t)((k * 16 + bcrow) * ROWX + btoff + nt * 32);
            uint32_t rh[4], rl[4];
            ldm_x4t(rh, smb + XHo + off);
            ldm_x4t(rl, smb + XLo + off);
            #pragma unroll
            for (int jf = 0; jf < 2; jf++) {
                mma_f16(acc[jf][2*nt],   Ah[jf], rh);        // w * xhi
                mma_f16(acc[jf][2*nt+1], Ah[jf], rh + 2);
                mma_f16(acc[jf][2*nt],   Ah[jf], rl);        // w * xlo
                mma_f16(acc[jf][2*nt+1], Ah[jf], rl + 2);
            }
        }
    }

    // ---- epilogue: streaming float2 stores (out never re-read) ----
    int g = lane >> 2, q2 = (lane & 3) * 2;
    #pragma unroll
    for (int jf = 0; jf < 2; jf++) {
        int j = j0 + wj * 32 + jf * 16 + g;
        #pragma unroll
        for (int nf = 0; nf < 8; nf++) {
            int t = t0 + wt * 64 + nf * 8 + q2;
            if (j < D1_) {
                float2 v0 = make_float2(acc[jf][nf][0], acc[jf][nf][1]);
                __stcs((float2*)(out + ((size_t)b * D1_ + j) * T_ + t), v0);
            }
            if (j + 8 < D1_) {
                float2 v1 = make_float2(acc[jf][nf][2], acc[jf][nf][3]);
                __stcs((float2*)(out + ((size_t)b * D1_ + j + 8) * T_ + t), v1);
            }
        }
    }
}

// ---------------- launch ----------------
extern "C" void kernel_launch(void* const* d_in, const int* in_sizes, int n_in,
                              void* d_out, int out_size) {
    const float* X   = (const float*)d_in[0];   // [64, 60, 4096]
    const float* zre = (const float*)d_in[1];   // [270, 32, 32]
    const float* zim = (const float*)d_in[2];   // [270, 32, 32]
    const float* loc = (const float*)d_in[3];   // [60, 2]
    float* out = (float*)d_out;                 // [64, 270, 4096]

    trig_kernel<<<(64 * 1024 + 255) / 256, 256>>>(loc);
    weights_kernel<<<D1_ / JB, 256>>>(zre, zim);
    dim3 grid(T_ / 128, 3, B_);   // x,y fastest -> X[b] (1MB) L2-resident across jb
    mma_kernel<<<grid, 192>>>(X, out);
}